// round 5
// baseline (speedup 1.0000x reference)
#include <cuda_runtime.h>
#include <cuda_bf16.h>
#include <math.h>

// Problem constants
#define T_TOK   2048
#define HDIM    1024
#define NEXP    16
#define IDIM    512
#define ISDIM   1024
#define TOPK    4
#define NGRP    4
#define EPG     4
#define SCALE_F 2.5f

// ---------------- scratch (__device__ globals; no allocation) ----------------
// NOTE: these are ONLY referenced (a) inside device code, or (b) via
// cudaGetSymbolAddress on the host. NEVER passed directly as kernel args
// from host (host sees the shadow symbol; on GB300 ATS that silently reads
// host memory instead of faulting — the R1-R4 bug).
__device__ int   g_isbf16;
__device__ float c_x  [(size_t)T_TOK * HDIM];
__device__ float c_Wg [NEXP * HDIM];
__device__ float c_bias[NEXP];
__device__ float c_W1 [(size_t)NEXP * IDIM * HDIM];
__device__ float c_W2 [(size_t)NEXP * HDIM * IDIM];
__device__ float c_Ws1[(size_t)ISDIM * HDIM];
__device__ float c_Ws2[(size_t)HDIM * ISDIM];

__device__ float g_cw [T_TOK * NEXP];
__device__ float g_hid[(size_t)NEXP * T_TOK * IDIM];
__device__ float g_y  [(size_t)NEXP * T_TOK * HDIM];
__device__ float g_hs [(size_t)T_TOK * ISDIM];
__device__ float g_ys [(size_t)T_TOK * HDIM];

// ---------------- dtype probe ----------------
__global__ void probe_kernel(const unsigned int* __restrict__ xw) {
    if (threadIdx.x == 0 && blockIdx.x == 0) {
        int cnt = 0;
        for (int i = 0; i < 256; i++) {
            unsigned int lo = xw[i] & 0xFFFFu;
            if (((lo >> 13) & 3u) == 1u) cnt++;   // bf16 ~N(0,1): exp top bits "01" with P~.95
        }
        g_isbf16 = (cnt > 150) ? 1 : 0;
    }
}

// ---------------- input conversion ----------------
__global__ void convert_kernel(const void* __restrict__ src, float* __restrict__ dst, int n) {
    int i = blockIdx.x * 256 + threadIdx.x;
    int stride = gridDim.x * 256;
    if (g_isbf16) {
        const __nv_bfloat16* s = (const __nv_bfloat16*)src;
        for (; i < n; i += stride) dst[i] = __bfloat162float(s[i]);
    } else {
        const float* s = (const float*)src;
        for (; i < n; i += stride) dst[i] = s[i];
    }
}

// ---------------- router (device-symbol access only; valid) ----------------
__global__ void router_kernel() {
    int t = blockIdx.x;
    __shared__ float sx[HDIM];
    __shared__ float slog[NEXP];
    const float* xr = c_x + (size_t)t * HDIM;
    for (int i = threadIdx.x; i < HDIM; i += 128) sx[i] = xr[i];
    __syncthreads();
    int warp = threadIdx.x >> 5, lane = threadIdx.x & 31;
    for (int eo = 0; eo < 4; eo++) {
        int e = warp * 4 + eo;
        const float* w = c_Wg + (size_t)e * HDIM;
        float p = 0.f;
        for (int i = lane; i < HDIM; i += 32) p += sx[i] * w[i];
        #pragma unroll
        for (int o = 16; o; o >>= 1) p += __shfl_xor_sync(0xffffffffu, p, o);
        if (lane == 0) slog[e] = p;
    }
    __syncthreads();
    if (threadIdx.x == 0) {
        float sc[NEXP], ch[NEXP];
        #pragma unroll
        for (int e = 0; e < NEXP; e++) {
            sc[e] = 1.f / (1.f + expf(-slog[e]));
            ch[e] = sc[e] + c_bias[e];
        }
        float gs[NGRP];
        #pragma unroll
        for (int g = 0; g < NGRP; g++) {
            float m1 = -1e30f, m2 = -1e30f;
            #pragma unroll
            for (int k = 0; k < EPG; k++) {
                float v = ch[g*EPG + k];
                if (v > m1) { m2 = m1; m1 = v; } else if (v > m2) { m2 = v; }
            }
            gs[g] = m1 + m2;
        }
        int g1 = 0;
        for (int g = 1; g < NGRP; g++) if (gs[g] > gs[g1]) g1 = g;
        int g2 = -1;
        for (int g = 0; g < NGRP; g++) { if (g == g1) continue; if (g2 < 0 || gs[g] > gs[g2]) g2 = g; }
        float masked[NEXP];
        #pragma unroll
        for (int e = 0; e < NEXP; e++) {
            int g = e >> 2;
            masked[e] = (g == g1 || g == g2) ? ch[e] : 0.f;
        }
        int idx[TOPK]; float tw[TOPK]; float wsum = 0.f;
        #pragma unroll
        for (int j = 0; j < TOPK; j++) {
            int b = 0;
            for (int e = 1; e < NEXP; e++) if (masked[e] > masked[b]) b = e;
            idx[j] = b; tw[j] = sc[b]; wsum += sc[b];
            masked[b] = -1e30f;
        }
        float inv = SCALE_F / (wsum + 1e-20f);
        float cw[NEXP];
        #pragma unroll
        for (int e = 0; e < NEXP; e++) cw[e] = 0.f;
        #pragma unroll
        for (int j = 0; j < TOPK; j++) cw[idx[j]] += tw[j] * inv;
        #pragma unroll
        for (int e = 0; e < NEXP; e++) g_cw[t*NEXP + e] = cw[e];
    }
}

// ---------------- dense tiled fp32 GEMM (BM=BN=64, BK=32, 4x4 microtile) ----------------
template<bool RELU2>
__global__ void gemm64d(const float* __restrict__ A, const float* __restrict__ W,
                        float* __restrict__ C, int K, int Ntot,
                        size_t aStride, size_t wStride, size_t cStride) {
    int e = blockIdx.z;
    const float* Ab = A + (size_t)e * aStride;
    const float* Wb = W + (size_t)e * wStride;
    float*       Cb = C + (size_t)e * cStride;
    int row0 = blockIdx.x * 64;
    int n0   = blockIdx.y * 64;

    __shared__ float As[32][64];
    __shared__ float Bs[32][64];

    int tid = threadIdx.x;
    int tx = tid & 15, ty = tid >> 4;
    int lm = tid >> 2;
    int lk = (tid & 3) * 8;

    const float* arow = Ab + (size_t)(row0 + lm) * K;
    const float* brow = Wb + (size_t)(n0  + lm) * K;

    float acc[4][4];
    #pragma unroll
    for (int i = 0; i < 4; i++)
        #pragma unroll
        for (int j = 0; j < 4; j++) acc[i][j] = 0.f;

    for (int k0 = 0; k0 < K; k0 += 32) {
        #pragma unroll
        for (int q = 0; q < 2; q++) {
            float4 v = *(const float4*)(arow + k0 + lk + q*4);
            As[lk+q*4+0][lm] = v.x; As[lk+q*4+1][lm] = v.y;
            As[lk+q*4+2][lm] = v.z; As[lk+q*4+3][lm] = v.w;
        }
        #pragma unroll
        for (int q = 0; q < 2; q++) {
            float4 v = *(const float4*)(brow + k0 + lk + q*4);
            Bs[lk+q*4+0][lm] = v.x; Bs[lk+q*4+1][lm] = v.y;
            Bs[lk+q*4+2][lm] = v.z; Bs[lk+q*4+3][lm] = v.w;
        }
        __syncthreads();
        #pragma unroll
        for (int k = 0; k < 32; k++) {
            float4 a = *(const float4*)&As[k][ty*4];
            float4 b = *(const float4*)&Bs[k][tx*4];
            acc[0][0] += a.x*b.x; acc[0][1] += a.x*b.y; acc[0][2] += a.x*b.z; acc[0][3] += a.x*b.w;
            acc[1][0] += a.y*b.x; acc[1][1] += a.y*b.y; acc[1][2] += a.y*b.z; acc[1][3] += a.y*b.w;
            acc[2][0] += a.z*b.x; acc[2][1] += a.z*b.y; acc[2][2] += a.z*b.z; acc[2][3] += a.z*b.w;
            acc[3][0] += a.w*b.x; acc[3][1] += a.w*b.y; acc[3][2] += a.w*b.z; acc[3][3] += a.w*b.w;
        }
        __syncthreads();
    }

    #pragma unroll
    for (int i = 0; i < 4; i++) {
        int r = row0 + ty*4 + i;
        float v0 = acc[i][0], v1 = acc[i][1], v2 = acc[i][2], v3 = acc[i][3];
        if (RELU2) {
            v0 = fmaxf(v0, 0.f); v0 *= v0;
            v1 = fmaxf(v1, 0.f); v1 *= v1;
            v2 = fmaxf(v2, 0.f); v2 *= v2;
            v3 = fmaxf(v3, 0.f); v3 *= v3;
        }
        float4 o; o.x = v0; o.y = v1; o.z = v2; o.w = v3;
        *(float4*)&Cb[(size_t)r * Ntot + n0 + tx*4] = o;
    }
}

// ---------------- combine + dtype-branched output write ----------------
__global__ void combine_kernel(void* __restrict__ out) {
    int t = blockIdx.x;
    __shared__ float w[NEXP];
    if (threadIdx.x < NEXP) w[threadIdx.x] = g_cw[t*NEXP + threadIdx.x];
    __syncthreads();
    int h = threadIdx.x * 4;
    float4 o = *(const float4*)&g_ys[(size_t)t * HDIM + h];
    #pragma unroll
    for (int e = 0; e < NEXP; e++) {
        float we = w[e];
        if (we != 0.f) {
            float4 v = *(const float4*)&g_y[((size_t)e * T_TOK + t) * HDIM + h];
            o.x += we * v.x; o.y += we * v.y; o.z += we * v.z; o.w += we * v.w;
        }
    }
    size_t base = (size_t)t * HDIM + h;
    if (g_isbf16) {
        __nv_bfloat16* ob = (__nv_bfloat16*)out;
        ob[base+0] = __float2bfloat16(o.x);
        ob[base+1] = __float2bfloat16(o.y);
        ob[base+2] = __float2bfloat16(o.z);
        ob[base+3] = __float2bfloat16(o.w);
    } else {
        float* of = (float*)out;
        *(float4*)&of[base] = o;
    }
}

// ---------------- launch ----------------
extern "C" void kernel_launch(void* const* d_in, const int* in_sizes, int n_in,
                              void* d_out, int out_size) {
    // Bind inputs by element count; fall back to positional if sizes don't match.
    const void *x = 0, *Wg = 0, *bias = 0, *W1 = 0, *W2 = 0, *Ws1 = 0, *Ws2 = 0;
    for (int i = 0; i < n_in; i++) {
        int sz = in_sizes[i];
        const void* p = d_in[i];
        if      (sz == 2097152) { x = p; }
        else if (sz == 16384)   { Wg = p; }
        else if (sz == 16)      { bias = p; }
        else if (sz == 8388608) { if (!W1) W1 = p; else W2 = p; }
        else if (sz == 1048576) { if (!Ws1) Ws1 = p; else Ws2 = p; }
    }
    if (!x || !Wg || !bias || !W1 || !W2 || !Ws1 || !Ws2) {
        x = d_in[0]; Wg = d_in[1]; bias = d_in[2];
        W1 = d_in[3]; W2 = d_in[4]; Ws1 = d_in[5]; Ws2 = d_in[6];
    }

    // Resolve REAL device addresses of scratch symbols (host must never pass
    // __device__ symbols directly as kernel args).
    float *p_x, *p_Wg, *p_bias, *p_W1, *p_W2, *p_Ws1, *p_Ws2;
    float *p_hid, *p_y, *p_hs, *p_ys;
    cudaGetSymbolAddress((void**)&p_x,   c_x);
    cudaGetSymbolAddress((void**)&p_Wg,  c_Wg);
    cudaGetSymbolAddress((void**)&p_bias,c_bias);
    cudaGetSymbolAddress((void**)&p_W1,  c_W1);
    cudaGetSymbolAddress((void**)&p_W2,  c_W2);
    cudaGetSymbolAddress((void**)&p_Ws1, c_Ws1);
    cudaGetSymbolAddress((void**)&p_Ws2, c_Ws2);
    cudaGetSymbolAddress((void**)&p_hid, g_hid);
    cudaGetSymbolAddress((void**)&p_y,   g_y);
    cudaGetSymbolAddress((void**)&p_hs,  g_hs);
    cudaGetSymbolAddress((void**)&p_ys,  g_ys);

    probe_kernel<<<1, 32>>>((const unsigned int*)x);

    convert_kernel<<<512, 256>>>(x,    p_x,   T_TOK*HDIM);
    convert_kernel<<<64,  256>>>(Wg,   p_Wg,  NEXP*HDIM);
    convert_kernel<<<1,   256>>>(bias, p_bias, NEXP);
    convert_kernel<<<2048,256>>>(W1,   p_W1,  NEXP*IDIM*HDIM);
    convert_kernel<<<2048,256>>>(W2,   p_W2,  NEXP*HDIM*IDIM);
    convert_kernel<<<256, 256>>>(Ws1,  p_Ws1, ISDIM*HDIM);
    convert_kernel<<<256, 256>>>(Ws2,  p_Ws2, HDIM*ISDIM);

    router_kernel<<<T_TOK, 128>>>();

    // expert up (dense): hid[e,t,:] = relu2( x[t] @ W1[e]^T )  (A shared across e)
    gemm64d<true ><<<dim3(T_TOK/64, IDIM/64,  NEXP), 256>>>(p_x,   p_W1,  p_hid, HDIM,  IDIM,
                                                            0, (size_t)IDIM*HDIM, (size_t)T_TOK*IDIM);
    // expert down (dense): y[e,t,:] = hid[e,t] @ W2[e]^T
    gemm64d<false><<<dim3(T_TOK/64, HDIM/64,  NEXP), 256>>>(p_hid, p_W2,  p_y,   IDIM,  HDIM,
                                                            (size_t)T_TOK*IDIM, (size_t)HDIM*IDIM, (size_t)T_TOK*HDIM);
    // shared up: hs[t] = relu2( x[t] @ Ws1^T )
    gemm64d<true ><<<dim3(T_TOK/64, ISDIM/64, 1),    256>>>(p_x,   p_Ws1, p_hs,  HDIM,  ISDIM, 0, 0, 0);
    // shared down: ys[t] = hs[t] @ Ws2^T
    gemm64d<false><<<dim3(T_TOK/64, HDIM/64,  1),    256>>>(p_hs,  p_Ws2, p_ys,  ISDIM, HDIM,  0, 0, 0);

    combine_kernel<<<T_TOK, 256>>>(d_out);
}

// round 6
// speedup vs baseline: 2.5921x; 2.5921x over previous
#include <cuda_runtime.h>
#include <cuda_bf16.h>
#include <math.h>

// Problem constants
#define T_TOK   2048
#define HDIM    1024
#define NEXP    16
#define IDIM    512
#define ISDIM   1024
#define TOPK    4
#define NGRP    4
#define EPG     4
#define SCALE_F 2.5f

#define BM 64
#define MAXSLOTS (8192 + NEXP*BM)   // 9216: worst-case padded slot count

// ---------------- scratch (__device__ globals; device-code refs or cudaGetSymbolAddress only) ----------------
__device__ float g_topw[T_TOK*TOPK];
__device__ int   g_tope[T_TOK*TOPK];
__device__ int   g_slotmap[T_TOK*TOPK];
__device__ int   g_list[MAXSLOTS];
__device__ int   g_cnt[NEXP];
__device__ int   g_cur[NEXP];
__device__ int   g_off[NEXP+1];
__device__ float g_hid[(size_t)MAXSLOTS * IDIM];
__device__ float g_y  [(size_t)MAXSLOTS * HDIM];
__device__ float g_hs [(size_t)T_TOK * ISDIM];
__device__ float g_ys [(size_t)T_TOK * HDIM];

// ---------------- init ----------------
__global__ void init_kernel() {
    int i = blockIdx.x * 256 + threadIdx.x;
    if (i < NEXP) { g_cnt[i] = 0; g_cur[i] = 0; }
    if (i < MAXSLOTS) g_list[i] = -1;
}

// ---------------- router ----------------
__global__ void router_kernel(const float* __restrict__ x,
                              const float* __restrict__ Wg,
                              const float* __restrict__ bias) {
    int t = blockIdx.x;
    __shared__ float sx[HDIM];
    __shared__ float slog[NEXP];
    const float* xr = x + (size_t)t * HDIM;
    for (int i = threadIdx.x; i < HDIM; i += 128) sx[i] = xr[i];
    __syncthreads();
    int warp = threadIdx.x >> 5, lane = threadIdx.x & 31;
    for (int eo = 0; eo < 4; eo++) {
        int e = warp * 4 + eo;
        const float* w = Wg + (size_t)e * HDIM;
        float p = 0.f;
        for (int i = lane; i < HDIM; i += 32) p += sx[i] * w[i];
        #pragma unroll
        for (int o = 16; o; o >>= 1) p += __shfl_xor_sync(0xffffffffu, p, o);
        if (lane == 0) slog[e] = p;
    }
    __syncthreads();
    if (threadIdx.x == 0) {
        float sc[NEXP], ch[NEXP];
        #pragma unroll
        for (int e = 0; e < NEXP; e++) {
            sc[e] = 1.f / (1.f + expf(-slog[e]));
            ch[e] = sc[e] + bias[e];
        }
        float gs[NGRP];
        #pragma unroll
        for (int g = 0; g < NGRP; g++) {
            float m1 = -1e30f, m2 = -1e30f;
            #pragma unroll
            for (int k = 0; k < EPG; k++) {
                float v = ch[g*EPG + k];
                if (v > m1) { m2 = m1; m1 = v; } else if (v > m2) { m2 = v; }
            }
            gs[g] = m1 + m2;
        }
        int g1 = 0;
        for (int g = 1; g < NGRP; g++) if (gs[g] > gs[g1]) g1 = g;
        int g2 = -1;
        for (int g = 0; g < NGRP; g++) { if (g == g1) continue; if (g2 < 0 || gs[g] > gs[g2]) g2 = g; }
        float masked[NEXP];
        #pragma unroll
        for (int e = 0; e < NEXP; e++) {
            int g = e >> 2;
            masked[e] = (g == g1 || g == g2) ? ch[e] : 0.f;
        }
        int idx[TOPK]; float tw[TOPK]; float wsum = 0.f;
        #pragma unroll
        for (int j = 0; j < TOPK; j++) {
            int b = 0;
            for (int e = 1; e < NEXP; e++) if (masked[e] > masked[b]) b = e;
            idx[j] = b; tw[j] = sc[b]; wsum += sc[b];
            masked[b] = -1e30f;
        }
        float inv = SCALE_F / (wsum + 1e-20f);
        #pragma unroll
        for (int j = 0; j < TOPK; j++) {
            g_topw[t*TOPK + j] = tw[j] * inv;
            g_tope[t*TOPK + j] = idx[j];
            atomicAdd(&g_cnt[idx[j]], 1);
        }
    }
}

// ---------------- offsets (padded to BM) ----------------
__global__ void scan_kernel() {
    if (threadIdx.x == 0) {
        int o = 0;
        for (int e = 0; e < NEXP; e++) {
            g_off[e] = o;
            o += ((g_cnt[e] + BM - 1) / BM) * BM;
        }
        g_off[NEXP] = o;
    }
}

// ---------------- fill compact lists ----------------
__global__ void fill_kernel() {
    int t = blockIdx.x * 256 + threadIdx.x;
    if (t >= T_TOK) return;
    for (int j = 0; j < TOPK; j++) {
        int e = g_tope[t*TOPK + j];
        int pos = atomicAdd(&g_cur[e], 1);
        int slot = g_off[e] + pos;
        g_list[slot] = t;
        g_slotmap[t*TOPK + j] = slot;
    }
}

// ---------------- tiled fp32 GEMM (BM=BN=64, BK=32, 4x4 microtile) ----------------
// EXPERT: rows are global slots; expert from g_off; W base += e*wstride.
// GATHER: A row via g_list token gather; -1 slots -> zero rows.
template<bool GATHER, bool EXPERT, bool RELU2>
__global__ void gemm64(const float* __restrict__ A, const float* __restrict__ W,
                       float* __restrict__ C, int K, int Ntot, size_t wstride) {
    int row0 = blockIdx.x * BM;
    int e = 0;
    if (EXPERT) {
        int tot = g_off[NEXP];
        if (row0 >= tot) return;
        while (row0 >= g_off[e+1]) e++;
    }
    const float* Wb = EXPERT ? (W + (size_t)e * wstride) : W;
    int n0 = blockIdx.y * 64;

    __shared__ float As[32][64];
    __shared__ float Bs[32][64];

    int tid = threadIdx.x;
    int tx = tid & 15, ty = tid >> 4;
    int lm = tid >> 2;           // 0..63
    int lk = (tid & 3) * 8;      // 0,8,16,24

    const float* arow;
    bool avalid = true;
    if (GATHER) {
        int tok = g_list[row0 + lm];
        avalid = (tok >= 0);
        arow = A + (size_t)(avalid ? tok : 0) * K;
    } else {
        arow = A + (size_t)(row0 + lm) * K;
    }
    const float* brow = Wb + (size_t)(n0 + lm) * K;

    float acc[4][4];
    #pragma unroll
    for (int i = 0; i < 4; i++)
        #pragma unroll
        for (int j = 0; j < 4; j++) acc[i][j] = 0.f;

    for (int k0 = 0; k0 < K; k0 += 32) {
        #pragma unroll
        for (int q = 0; q < 2; q++) {
            float4 v = avalid ? *(const float4*)(arow + k0 + lk + q*4)
                              : make_float4(0.f,0.f,0.f,0.f);
            As[lk+q*4+0][lm] = v.x; As[lk+q*4+1][lm] = v.y;
            As[lk+q*4+2][lm] = v.z; As[lk+q*4+3][lm] = v.w;
        }
        #pragma unroll
        for (int q = 0; q < 2; q++) {
            float4 v = *(const float4*)(brow + k0 + lk + q*4);
            Bs[lk+q*4+0][lm] = v.x; Bs[lk+q*4+1][lm] = v.y;
            Bs[lk+q*4+2][lm] = v.z; Bs[lk+q*4+3][lm] = v.w;
        }
        __syncthreads();
        #pragma unroll
        for (int k = 0; k < 32; k++) {
            float4 a = *(const float4*)&As[k][ty*4];
            float4 b = *(const float4*)&Bs[k][tx*4];
            acc[0][0] += a.x*b.x; acc[0][1] += a.x*b.y; acc[0][2] += a.x*b.z; acc[0][3] += a.x*b.w;
            acc[1][0] += a.y*b.x; acc[1][1] += a.y*b.y; acc[1][2] += a.y*b.z; acc[1][3] += a.y*b.w;
            acc[2][0] += a.z*b.x; acc[2][1] += a.z*b.y; acc[2][2] += a.z*b.z; acc[2][3] += a.z*b.w;
            acc[3][0] += a.w*b.x; acc[3][1] += a.w*b.y; acc[3][2] += a.w*b.z; acc[3][3] += a.w*b.w;
        }
        __syncthreads();
    }

    #pragma unroll
    for (int i = 0; i < 4; i++) {
        int r = row0 + ty*4 + i;
        float v0 = acc[i][0], v1 = acc[i][1], v2 = acc[i][2], v3 = acc[i][3];
        if (RELU2) {
            v0 = fmaxf(v0, 0.f); v0 *= v0;
            v1 = fmaxf(v1, 0.f); v1 *= v1;
            v2 = fmaxf(v2, 0.f); v2 *= v2;
            v3 = fmaxf(v3, 0.f); v3 *= v3;
        }
        float4 o; o.x = v0; o.y = v1; o.z = v2; o.w = v3;
        *(float4*)&C[(size_t)r * Ntot + n0 + tx*4] = o;
    }
}

// ---------------- combine: out[t] = ys[t] + sum_j w_j * y[slot_j] ----------------
__global__ void combine_kernel(float* __restrict__ out) {
    int t = blockIdx.x;
    int h = threadIdx.x * 4;
    float4 o = *(const float4*)&g_ys[(size_t)t * HDIM + h];
    #pragma unroll
    for (int j = 0; j < TOPK; j++) {
        int slot = g_slotmap[t*TOPK + j];
        float w = g_topw[t*TOPK + j];
        float4 v = *(const float4*)&g_y[(size_t)slot * HDIM + h];
        o.x += w * v.x; o.y += w * v.y; o.z += w * v.z; o.w += w * v.w;
    }
    *(float4*)&out[(size_t)t * HDIM + h] = o;
}

// ---------------- launch ----------------
extern "C" void kernel_launch(void* const* d_in, const int* in_sizes, int n_in,
                              void* d_out, int out_size) {
    // Bind inputs by element count (fp32 confirmed by R5 rel_err=1e-6).
    const float *x = 0, *Wg = 0, *bias = 0, *W1 = 0, *W2 = 0, *Ws1 = 0, *Ws2 = 0;
    for (int i = 0; i < n_in; i++) {
        int sz = in_sizes[i];
        const float* p = (const float*)d_in[i];
        if      (sz == 2097152) { x = p; }
        else if (sz == 16384)   { Wg = p; }
        else if (sz == 16)      { bias = p; }
        else if (sz == 8388608) { if (!W1) W1 = p; else W2 = p; }
        else if (sz == 1048576) { if (!Ws1) Ws1 = p; else Ws2 = p; }
    }
    if (!x || !Wg || !bias || !W1 || !W2 || !Ws1 || !Ws2) {
        x = (const float*)d_in[0]; Wg = (const float*)d_in[1]; bias = (const float*)d_in[2];
        W1 = (const float*)d_in[3]; W2 = (const float*)d_in[4];
        Ws1 = (const float*)d_in[5]; Ws2 = (const float*)d_in[6];
    }
    float* out = (float*)d_out;

    // Resolve REAL device addresses for scratch passed as kernel args.
    float *p_hid, *p_y, *p_hs, *p_ys;
    cudaGetSymbolAddress((void**)&p_hid, g_hid);
    cudaGetSymbolAddress((void**)&p_y,   g_y);
    cudaGetSymbolAddress((void**)&p_hs,  g_hs);
    cudaGetSymbolAddress((void**)&p_ys,  g_ys);

    init_kernel<<<(MAXSLOTS + 255) / 256, 256>>>();
    router_kernel<<<T_TOK, 128>>>(x, Wg, bias);
    scan_kernel<<<1, 32>>>();
    fill_kernel<<<(T_TOK + 255) / 256, 256>>>();

    // expert up: hid[slot] = relu2( x[g_list[slot]] @ W1[e]^T )
    gemm64<true,  true,  true ><<<dim3(MAXSLOTS/BM, IDIM/64), 256>>>(x,     W1,  p_hid, HDIM, IDIM, (size_t)IDIM*HDIM);
    // expert down: y[slot] = hid[slot] @ W2[e]^T
    gemm64<false, true,  false><<<dim3(MAXSLOTS/BM, HDIM/64), 256>>>(p_hid, W2,  p_y,   IDIM, HDIM, (size_t)HDIM*IDIM);
    // shared up: hs[t] = relu2( x[t] @ Ws1^T )
    gemm64<false, false, true ><<<dim3(T_TOK/BM,  ISDIM/64), 256>>>(x,     Ws1, p_hs,  HDIM, ISDIM, 0);
    // shared down: ys[t] = hs[t] @ Ws2^T
    gemm64<false, false, false><<<dim3(T_TOK/BM,  HDIM/64),  256>>>(p_hs,  Ws2, p_ys,  ISDIM, HDIM, 0);

    combine_kernel<<<T_TOK, 256>>>(out);
}

// round 7
// speedup vs baseline: 6.0281x; 2.3255x over previous
#include <cuda_runtime.h>
#include <cuda_bf16.h>
#include <math.h>
#include <stdint.h>

// Problem constants
#define T_TOK   2048
#define HDIM    1024
#define NEXP    16
#define IDIM    512
#define ISDIM   1024
#define TOPK    4
#define NGRP    4
#define EPG     4
#define SCALE_F 2.5f

#define BM 128
#define MAXSLOTS (8192 + NEXP*BM)   // 10240: worst-case padded slot count

// ---------------- scratch ----------------
__device__ float g_topw[T_TOK*TOPK];
__device__ int   g_tope[T_TOK*TOPK];
__device__ int   g_slotmap[T_TOK*TOPK];
__device__ int   g_list[MAXSLOTS];
__device__ int   g_cnt[NEXP];
__device__ int   g_cur[NEXP];
__device__ int   g_off[NEXP+1];
__device__ float g_hid[(size_t)MAXSLOTS * IDIM];
__device__ float g_y  [(size_t)MAXSLOTS * HDIM];
__device__ float g_hs [(size_t)T_TOK * ISDIM];
__device__ float g_ys [(size_t)T_TOK * HDIM];

// ---------------- init ----------------
__global__ void init_kernel() {
    int i = blockIdx.x * 256 + threadIdx.x;
    if (i < NEXP) { g_cnt[i] = 0; g_cur[i] = 0; }
    if (i < MAXSLOTS) g_list[i] = -1;
}

// ---------------- router ----------------
__global__ void router_kernel(const float* __restrict__ x,
                              const float* __restrict__ Wg,
                              const float* __restrict__ bias) {
    int t = blockIdx.x;
    __shared__ float sx[HDIM];
    __shared__ float slog[NEXP];
    const float* xr = x + (size_t)t * HDIM;
    for (int i = threadIdx.x; i < HDIM; i += 128) sx[i] = xr[i];
    __syncthreads();
    int warp = threadIdx.x >> 5, lane = threadIdx.x & 31;
    for (int eo = 0; eo < 4; eo++) {
        int e = warp * 4 + eo;
        const float* w = Wg + (size_t)e * HDIM;
        float p = 0.f;
        for (int i = lane; i < HDIM; i += 32) p += sx[i] * w[i];
        #pragma unroll
        for (int o = 16; o; o >>= 1) p += __shfl_xor_sync(0xffffffffu, p, o);
        if (lane == 0) slog[e] = p;
    }
    __syncthreads();
    if (threadIdx.x == 0) {
        float sc[NEXP], ch[NEXP];
        #pragma unroll
        for (int e = 0; e < NEXP; e++) {
            sc[e] = 1.f / (1.f + expf(-slog[e]));
            ch[e] = sc[e] + bias[e];
        }
        float gs[NGRP];
        #pragma unroll
        for (int g = 0; g < NGRP; g++) {
            float m1 = -1e30f, m2 = -1e30f;
            #pragma unroll
            for (int k = 0; k < EPG; k++) {
                float v = ch[g*EPG + k];
                if (v > m1) { m2 = m1; m1 = v; } else if (v > m2) { m2 = v; }
            }
            gs[g] = m1 + m2;
        }
        int g1 = 0;
        for (int g = 1; g < NGRP; g++) if (gs[g] > gs[g1]) g1 = g;
        int g2 = -1;
        for (int g = 0; g < NGRP; g++) { if (g == g1) continue; if (g2 < 0 || gs[g] > gs[g2]) g2 = g; }
        float masked[NEXP];
        #pragma unroll
        for (int e = 0; e < NEXP; e++) {
            int g = e >> 2;
            masked[e] = (g == g1 || g == g2) ? ch[e] : 0.f;
        }
        int idx[TOPK]; float tw[TOPK]; float wsum = 0.f;
        #pragma unroll
        for (int j = 0; j < TOPK; j++) {
            int b = 0;
            for (int e = 1; e < NEXP; e++) if (masked[e] > masked[b]) b = e;
            idx[j] = b; tw[j] = sc[b]; wsum += sc[b];
            masked[b] = -1e30f;
        }
        float inv = SCALE_F / (wsum + 1e-20f);
        #pragma unroll
        for (int j = 0; j < TOPK; j++) {
            g_topw[t*TOPK + j] = tw[j] * inv;
            g_tope[t*TOPK + j] = idx[j];
            atomicAdd(&g_cnt[idx[j]], 1);
        }
    }
}

// ---------------- offsets (padded to BM) ----------------
__global__ void scan_kernel() {
    if (threadIdx.x == 0) {
        int o = 0;
        for (int e = 0; e < NEXP; e++) {
            g_off[e] = o;
            o += ((g_cnt[e] + BM - 1) / BM) * BM;
        }
        g_off[NEXP] = o;
    }
}

// ---------------- fill compact lists ----------------
__global__ void fill_kernel() {
    int t = blockIdx.x * 256 + threadIdx.x;
    if (t >= T_TOK) return;
    for (int j = 0; j < TOPK; j++) {
        int e = g_tope[t*TOPK + j];
        int pos = atomicAdd(&g_cur[e], 1);
        int slot = g_off[e] + pos;
        g_list[slot] = t;
        g_slotmap[t*TOPK + j] = slot;
    }
}

// ---------------- tf32 helpers ----------------
__device__ __forceinline__ uint32_t f2tf32(float f) {
    uint32_t r;
    asm("cvt.rna.tf32.f32 %0, %1;" : "=r"(r) : "f"(f));
    return r;
}
__device__ __forceinline__ void mma_tf32(float* c, const uint32_t* a, const uint32_t* b) {
    asm volatile(
        "mma.sync.aligned.m16n8k8.row.col.f32.tf32.tf32.f32 "
        "{%0,%1,%2,%3}, {%4,%5,%6,%7}, {%8,%9}, {%0,%1,%2,%3};"
        : "+f"(c[0]), "+f"(c[1]), "+f"(c[2]), "+f"(c[3])
        : "r"(a[0]), "r"(a[1]), "r"(a[2]), "r"(a[3]), "r"(b[0]), "r"(b[1]));
}

// ---------------- tensor-core tf32 GEMM ----------------
// C[row][n] = act( A_row . W[n] ), A row-major [.,K], W row-major [N,K] (B^T => mma row.col)
// BM=128, BN=128, BK=16, 256 threads = 8 warps (2 m x 4 n), warp tile 64x32.
#define SMS 20   // smem k-stride (16 + 4 pad) -> conflict-free fragment loads
template<bool GATHER, bool EXPERT, bool RELU2>
__global__ void __launch_bounds__(256, 1)
gemm_tc(const float* __restrict__ A, const float* __restrict__ W,
        float* __restrict__ C, int K, int Ntot, size_t wstride) {
    int row0 = blockIdx.x * BM;
    int e = 0;
    if (EXPERT) {
        int tot = g_off[NEXP];
        if (row0 >= tot) return;
        while (row0 >= g_off[e+1]) e++;
    }
    const float* Wb = EXPERT ? (W + (size_t)e * wstride) : W;
    int n0 = blockIdx.y * 128;

    __shared__ uint32_t As[2][128 * SMS];
    __shared__ uint32_t Bs[2][128 * SMS];

    int tid  = threadIdx.x;
    int lane = tid & 31;
    int warp = tid >> 5;
    int wm = (warp & 1) * 64;        // warp m offset
    int wn = (warp >> 1) * 32;       // warp n offset

    // global loader mapping: each thread loads 8 A floats + 8 B floats per tile
    int lr  = tid >> 1;              // row 0..127
    int lks = (tid & 1) * 8;         // k offset 0/8

    const float* arow;
    bool avalid = true;
    if (GATHER) {
        int tok = g_list[row0 + lr];
        avalid = (tok >= 0);
        arow = A + (size_t)(avalid ? tok : 0) * K;
    } else {
        arow = A + (size_t)(row0 + lr) * K;
    }
    const float* brow = Wb + (size_t)(n0 + lr) * K;

    float acc[4][4][4];
    #pragma unroll
    for (int i = 0; i < 4; i++)
        #pragma unroll
        for (int j = 0; j < 4; j++)
            #pragma unroll
            for (int q = 0; q < 4; q++) acc[i][j][q] = 0.f;

    int nt = K / 16;
    float4 pa0, pa1, pb0, pb1;
    const float4 z4 = make_float4(0.f, 0.f, 0.f, 0.f);

    // preload tile 0
    pa0 = avalid ? *(const float4*)(arow + lks)     : z4;
    pa1 = avalid ? *(const float4*)(arow + lks + 4) : z4;
    pb0 = *(const float4*)(brow + lks);
    pb1 = *(const float4*)(brow + lks + 4);
    {
        uint32_t* a = &As[0][lr * SMS + lks];
        a[0]=f2tf32(pa0.x); a[1]=f2tf32(pa0.y); a[2]=f2tf32(pa0.z); a[3]=f2tf32(pa0.w);
        a[4]=f2tf32(pa1.x); a[5]=f2tf32(pa1.y); a[6]=f2tf32(pa1.z); a[7]=f2tf32(pa1.w);
        uint32_t* b = &Bs[0][lr * SMS + lks];
        b[0]=f2tf32(pb0.x); b[1]=f2tf32(pb0.y); b[2]=f2tf32(pb0.z); b[3]=f2tf32(pb0.w);
        b[4]=f2tf32(pb1.x); b[5]=f2tf32(pb1.y); b[6]=f2tf32(pb1.z); b[7]=f2tf32(pb1.w);
    }
    __syncthreads();

    int cur = 0;
    for (int kt = 0; kt < nt; kt++) {
        // prefetch next tile into registers (hidden under the mma work)
        if (kt + 1 < nt) {
            const float* ap = arow + (kt + 1) * 16 + lks;
            const float* bp = brow + (kt + 1) * 16 + lks;
            pa0 = avalid ? *(const float4*)(ap)     : z4;
            pa1 = avalid ? *(const float4*)(ap + 4) : z4;
            pb0 = *(const float4*)(bp);
            pb1 = *(const float4*)(bp + 4);
        }

        // compute: 2 k8 steps
        #pragma unroll
        for (int ks = 0; ks < 2; ks++) {
            int kk = ks * 8;
            uint32_t af[4][4], bf[4][2];
            int arow_f = (lane >> 2);
            int acol_f = kk + (lane & 3);
            #pragma unroll
            for (int mf = 0; mf < 4; mf++) {
                int r = wm + mf * 16 + arow_f;
                af[mf][0] = As[cur][ r      * SMS + acol_f];
                af[mf][1] = As[cur][(r + 8) * SMS + acol_f];
                af[mf][2] = As[cur][ r      * SMS + acol_f + 4];
                af[mf][3] = As[cur][(r + 8) * SMS + acol_f + 4];
            }
            #pragma unroll
            for (int nf = 0; nf < 4; nf++) {
                int r = wn + nf * 8 + (lane >> 2);
                bf[nf][0] = Bs[cur][r * SMS + acol_f];
                bf[nf][1] = Bs[cur][r * SMS + acol_f + 4];
            }
            #pragma unroll
            for (int mf = 0; mf < 4; mf++)
                #pragma unroll
                for (int nf = 0; nf < 4; nf++)
                    mma_tf32(acc[mf][nf], af[mf], bf[nf]);
        }

        // store prefetched tile into the other buffer
        if (kt + 1 < nt) {
            int nxt = cur ^ 1;
            uint32_t* a = &As[nxt][lr * SMS + lks];
            a[0]=f2tf32(pa0.x); a[1]=f2tf32(pa0.y); a[2]=f2tf32(pa0.z); a[3]=f2tf32(pa0.w);
            a[4]=f2tf32(pa1.x); a[5]=f2tf32(pa1.y); a[6]=f2tf32(pa1.z); a[7]=f2tf32(pa1.w);
            uint32_t* b = &Bs[nxt][lr * SMS + lks];
            b[0]=f2tf32(pb0.x); b[1]=f2tf32(pb0.y); b[2]=f2tf32(pb0.z); b[3]=f2tf32(pb0.w);
            b[4]=f2tf32(pb1.x); b[5]=f2tf32(pb1.y); b[6]=f2tf32(pb1.z); b[7]=f2tf32(pb1.w);
        }
        __syncthreads();
        cur ^= 1;
    }

    // epilogue
    #pragma unroll
    for (int mf = 0; mf < 4; mf++) {
        int r = row0 + wm + mf * 16 + (lane >> 2);
        #pragma unroll
        for (int nf = 0; nf < 4; nf++) {
            int c = n0 + wn + nf * 8 + 2 * (lane & 3);
            float v0 = acc[mf][nf][0], v1 = acc[mf][nf][1];
            float v2 = acc[mf][nf][2], v3 = acc[mf][nf][3];
            if (RELU2) {
                v0 = fmaxf(v0, 0.f); v0 *= v0;
                v1 = fmaxf(v1, 0.f); v1 *= v1;
                v2 = fmaxf(v2, 0.f); v2 *= v2;
                v3 = fmaxf(v3, 0.f); v3 *= v3;
            }
            float2 lo; lo.x = v0; lo.y = v1;
            float2 hi; hi.x = v2; hi.y = v3;
            *(float2*)&C[(size_t) r      * Ntot + c] = lo;
            *(float2*)&C[(size_t)(r + 8) * Ntot + c] = hi;
        }
    }
}

// ---------------- combine: out[t] = ys[t] + sum_j w_j * y[slot_j] ----------------
__global__ void combine_kernel(float* __restrict__ out) {
    int t = blockIdx.x;
    int h = threadIdx.x * 4;
    float4 o = *(const float4*)&g_ys[(size_t)t * HDIM + h];
    #pragma unroll
    for (int j = 0; j < TOPK; j++) {
        int slot = g_slotmap[t*TOPK + j];
        float w = g_topw[t*TOPK + j];
        float4 v = *(const float4*)&g_y[(size_t)slot * HDIM + h];
        o.x += w * v.x; o.y += w * v.y; o.z += w * v.z; o.w += w * v.w;
    }
    *(float4*)&out[(size_t)t * HDIM + h] = o;
}

// ---------------- launch ----------------
extern "C" void kernel_launch(void* const* d_in, const int* in_sizes, int n_in,
                              void* d_out, int out_size) {
    const float *x = 0, *Wg = 0, *bias = 0, *W1 = 0, *W2 = 0, *Ws1 = 0, *Ws2 = 0;
    for (int i = 0; i < n_in; i++) {
        int sz = in_sizes[i];
        const float* p = (const float*)d_in[i];
        if      (sz == 2097152) { x = p; }
        else if (sz == 16384)   { Wg = p; }
        else if (sz == 16)      { bias = p; }
        else if (sz == 8388608) { if (!W1) W1 = p; else W2 = p; }
        else if (sz == 1048576) { if (!Ws1) Ws1 = p; else Ws2 = p; }
    }
    if (!x || !Wg || !bias || !W1 || !W2 || !Ws1 || !Ws2) {
        x = (const float*)d_in[0]; Wg = (const float*)d_in[1]; bias = (const float*)d_in[2];
        W1 = (const float*)d_in[3]; W2 = (const float*)d_in[4];
        Ws1 = (const float*)d_in[5]; Ws2 = (const float*)d_in[6];
    }
    float* out = (float*)d_out;

    float *p_hid, *p_y, *p_hs, *p_ys;
    cudaGetSymbolAddress((void**)&p_hid, g_hid);
    cudaGetSymbolAddress((void**)&p_y,   g_y);
    cudaGetSymbolAddress((void**)&p_hs,  g_hs);
    cudaGetSymbolAddress((void**)&p_ys,  g_ys);

    init_kernel<<<(MAXSLOTS + 255) / 256, 256>>>();
    router_kernel<<<T_TOK, 128>>>(x, Wg, bias);
    scan_kernel<<<1, 32>>>();
    fill_kernel<<<(T_TOK + 255) / 256, 256>>>();

    // expert up: hid[slot] = relu2( x[g_list[slot]] @ W1[e]^T )
    gemm_tc<true,  true,  true ><<<dim3(MAXSLOTS/BM, IDIM/128),  256>>>(x,     W1,  p_hid, HDIM,  IDIM,  (size_t)IDIM*HDIM);
    // expert down: y[slot] = hid[slot] @ W2[e]^T
    gemm_tc<false, true,  false><<<dim3(MAXSLOTS/BM, HDIM/128),  256>>>(p_hid, W2,  p_y,   IDIM,  HDIM,  (size_t)HDIM*IDIM);
    // shared up: hs[t] = relu2( x[t] @ Ws1^T )
    gemm_tc<false, false, true ><<<dim3(T_TOK/BM,   ISDIM/128), 256>>>(x,     Ws1, p_hs,  HDIM,  ISDIM, 0);
    // shared down: ys[t] = hs[t] @ Ws2^T
    gemm_tc<false, false, false><<<dim3(T_TOK/BM,   HDIM/128),  256>>>(p_hs,  Ws2, p_ys,  ISDIM, HDIM,  0);

    combine_kernel<<<T_TOK, 256>>>(out);
}

// round 9
// speedup vs baseline: 9.8880x; 1.6403x over previous
#include <cuda_runtime.h>
#include <cuda_fp16.h>
#include <math.h>
#include <stdint.h>

// Problem constants
#define T_TOK   2048
#define HDIM    1024
#define NEXP    16
#define IDIM    512
#define ISDIM   1024
#define TOPK    4
#define NGRP    4
#define EPG     4
#define SCALE_F 2.5f

#define BM 128
#define BN 128
#define BK 32
#define MAXSLOTS (8192 + NEXP*BM)   // 10240
#define SMS 40                       // smem stride in halves (32 + 8 pad) -> conflict-free

// ---------------- scratch (__device__ globals; device refs or cudaGetSymbolAddress only) ----------------
__device__ float  g_topw[T_TOK*TOPK];
__device__ int    g_tope[T_TOK*TOPK];
__device__ int    g_slotmap[T_TOK*TOPK];
__device__ int    g_list[MAXSLOTS];
__device__ int    g_cnt[NEXP];
__device__ int    g_cur[NEXP];
__device__ int    g_off[NEXP+1];

// fp16 converted operands
__device__ __half h_x  [(size_t)T_TOK * HDIM];
__device__ __half h_W1 [(size_t)NEXP * IDIM * HDIM];
__device__ __half h_W2 [(size_t)NEXP * HDIM * IDIM];
__device__ __half h_Ws1[(size_t)ISDIM * HDIM];
__device__ __half h_Ws2[(size_t)HDIM * ISDIM];

// intermediates
__device__ __half g_hid[(size_t)MAXSLOTS * IDIM];   // fp16 (re-rounded like tf32 path)
__device__ float  g_y  [(size_t)MAXSLOTS * HDIM];
__device__ __half g_hs [(size_t)T_TOK * ISDIM];
__device__ float  g_ys [(size_t)T_TOK * HDIM];

// ---------------- helpers ----------------
__device__ __forceinline__ uint32_t smem_u32(const void* p) {
    uint32_t a;
    asm("{ .reg .u64 t; cvta.to.shared.u64 t, %1; cvt.u32.u64 %0, t; }" : "=r"(a) : "l"(p));
    return a;
}
__device__ __forceinline__ void cp16(uint32_t dst, const void* src) {
    asm volatile("cp.async.cg.shared.global [%0], [%1], 16;" :: "r"(dst), "l"(src));
}
__device__ __forceinline__ void mma_f16(float* c, const uint32_t* a, const uint32_t* b) {
    asm volatile(
        "mma.sync.aligned.m16n8k16.row.col.f32.f16.f16.f32 "
        "{%0,%1,%2,%3}, {%4,%5,%6,%7}, {%8,%9}, {%0,%1,%2,%3};"
        : "+f"(c[0]), "+f"(c[1]), "+f"(c[2]), "+f"(c[3])
        : "r"(a[0]), "r"(a[1]), "r"(a[2]), "r"(a[3]), "r"(b[0]), "r"(b[1]));
}

// ---------------- fp32 -> fp16 conversion ----------------
__global__ void cvt_kernel(const float* __restrict__ src, __half* __restrict__ dst, int n4) {
    int i = blockIdx.x * 256 + threadIdx.x;
    int stride = gridDim.x * 256;
    for (; i < n4; i += stride) {
        float4 v = *(const float4*)(src + (size_t)i * 4);
        __half2 lo = __floats2half2_rn(v.x, v.y);
        __half2 hi = __floats2half2_rn(v.z, v.w);
        uint2 u;
        u.x = *(uint32_t*)&lo;
        u.y = *(uint32_t*)&hi;
        *(uint2*)(dst + (size_t)i * 4) = u;
    }
}

// ---------------- init ----------------
__global__ void init_kernel() {
    int i = blockIdx.x * 256 + threadIdx.x;
    if (i < NEXP) { g_cnt[i] = 0; g_cur[i] = 0; }
    if (i < MAXSLOTS) g_list[i] = -1;
}

// ---------------- router (fp32 inputs, unchanged math) ----------------
__global__ void router_kernel(const float* __restrict__ x,
                              const float* __restrict__ Wg,
                              const float* __restrict__ bias) {
    int t = blockIdx.x;
    __shared__ float sx[HDIM];
    __shared__ float slog[NEXP];
    const float* xr = x + (size_t)t * HDIM;
    for (int i = threadIdx.x; i < HDIM; i += 128) sx[i] = xr[i];
    __syncthreads();
    int warp = threadIdx.x >> 5, lane = threadIdx.x & 31;
    for (int eo = 0; eo < 4; eo++) {
        int e = warp * 4 + eo;
        const float* w = Wg + (size_t)e * HDIM;
        float p = 0.f;
        for (int i = lane; i < HDIM; i += 32) p += sx[i] * w[i];
        #pragma unroll
        for (int o = 16; o; o >>= 1) p += __shfl_xor_sync(0xffffffffu, p, o);
        if (lane == 0) slog[e] = p;
    }
    __syncthreads();
    if (threadIdx.x == 0) {
        float sc[NEXP], ch[NEXP];
        #pragma unroll
        for (int e = 0; e < NEXP; e++) {
            sc[e] = 1.f / (1.f + expf(-slog[e]));
            ch[e] = sc[e] + bias[e];
        }
        float gs[NGRP];
        #pragma unroll
        for (int g = 0; g < NGRP; g++) {
            float m1 = -1e30f, m2 = -1e30f;
            #pragma unroll
            for (int k = 0; k < EPG; k++) {
                float v = ch[g*EPG + k];
                if (v > m1) { m2 = m1; m1 = v; } else if (v > m2) { m2 = v; }
            }
            gs[g] = m1 + m2;
        }
        int g1 = 0;
        for (int g = 1; g < NGRP; g++) if (gs[g] > gs[g1]) g1 = g;
        int g2 = -1;
        for (int g = 0; g < NGRP; g++) { if (g == g1) continue; if (g2 < 0 || gs[g] > gs[g2]) g2 = g; }
        float masked[NEXP];
        #pragma unroll
        for (int e = 0; e < NEXP; e++) {
            int g = e >> 2;
            masked[e] = (g == g1 || g == g2) ? ch[e] : 0.f;
        }
        int idx[TOPK]; float tw[TOPK]; float wsum = 0.f;
        #pragma unroll
        for (int j = 0; j < TOPK; j++) {
            int b = 0;
            for (int e = 1; e < NEXP; e++) if (masked[e] > masked[b]) b = e;
            idx[j] = b; tw[j] = sc[b]; wsum += sc[b];
            masked[b] = -1e30f;
        }
        float inv = SCALE_F / (wsum + 1e-20f);
        #pragma unroll
        for (int j = 0; j < TOPK; j++) {
            g_topw[t*TOPK + j] = tw[j] * inv;
            g_tope[t*TOPK + j] = idx[j];
            atomicAdd(&g_cnt[idx[j]], 1);
        }
    }
}

__global__ void scan_kernel() {
    if (threadIdx.x == 0) {
        int o = 0;
        for (int e = 0; e < NEXP; e++) {
            g_off[e] = o;
            o += ((g_cnt[e] + BM - 1) / BM) * BM;
        }
        g_off[NEXP] = o;
    }
}

__global__ void fill_kernel() {
    int t = blockIdx.x * 256 + threadIdx.x;
    if (t >= T_TOK) return;
    for (int j = 0; j < TOPK; j++) {
        int e = g_tope[t*TOPK + j];
        int pos = atomicAdd(&g_cur[e], 1);
        int slot = g_off[e] + pos;
        g_list[slot] = t;
        g_slotmap[t*TOPK + j] = slot;
    }
}

// ---------------- fp16 tensor-core GEMM ----------------
// C[row][n] = act( A_row . W[n] ); A [.,K] fp16 row-major, W [N,K] fp16 row-major.
// BM=BN=128, BK=32, 256 threads = 8 warps (2m x 4n), warp tile 64x32.
// Double-buffered cp.async pipeline.
template<bool GATHER, bool EXPERT, bool RELU2, typename CT>
__global__ void __launch_bounds__(256)
gemm_h(const __half* __restrict__ A, const __half* __restrict__ W,
       CT* __restrict__ C, int K, int Ntot, size_t wstride) {
    int row0 = blockIdx.x * BM;
    int e = 0;
    if (EXPERT) {
        int tot = g_off[NEXP];
        if (row0 >= tot) return;
        while (row0 >= g_off[e+1]) e++;
    }
    const __half* Wb = EXPERT ? (W + (size_t)e * wstride) : W;
    int n0 = blockIdx.y * BN;

    __shared__ __align__(16) __half As[2][128 * SMS];
    __shared__ __align__(16) __half Bs[2][128 * SMS];

    int tid  = threadIdx.x;
    int lane = tid & 31;
    int warp = tid >> 5;
    int wm = (warp & 1) * 64;
    int wn = (warp >> 1) * 32;

    // loader: thread owns one row, two 16B chunks (16 halves)
    int lrow = tid >> 1;
    int lq   = (tid & 1) * 16;       // half offset of first chunk (0 or 16)

    const __half* arow;
    if (GATHER) {
        int tok = g_list[row0 + lrow];
        arow = A + (size_t)(tok >= 0 ? tok : 0) * K;   // pad rows: junk, never read
    } else {
        arow = A + (size_t)(row0 + lrow) * K;
    }
    const __half* brow = Wb + (size_t)(n0 + lrow) * K;

    uint32_t aBase[2] = { smem_u32(&As[0][0]), smem_u32(&As[1][0]) };
    uint32_t bBase[2] = { smem_u32(&Bs[0][0]), smem_u32(&Bs[1][0]) };
    uint32_t dOffB = (uint32_t)(lrow * SMS + lq) * 2;   // byte offset in tile

    float acc[4][4][4];
    #pragma unroll
    for (int i = 0; i < 4; i++)
        #pragma unroll
        for (int j = 0; j < 4; j++)
            #pragma unroll
            for (int q = 0; q < 4; q++) acc[i][j][q] = 0.f;

    int nt = K / BK;

    // prologue: tile 0
    {
        const __half* as = arow + lq;
        const __half* bs = brow + lq;
        cp16(aBase[0] + dOffB,      as);
        cp16(aBase[0] + dOffB + 16, as + 8);
        cp16(bBase[0] + dOffB,      bs);
        cp16(bBase[0] + dOffB + 16, bs + 8);
        asm volatile("cp.async.commit_group;");
    }

    int g  = lane >> 2;
    int c2 = (lane & 3) * 2;

    for (int kt = 0; kt < nt; kt++) {
        int buf = kt & 1;
        if (kt + 1 < nt) {
            int nb = (kt + 1) & 1;
            const __half* as = arow + (kt + 1) * BK + lq;
            const __half* bs = brow + (kt + 1) * BK + lq;
            cp16(aBase[nb] + dOffB,      as);
            cp16(aBase[nb] + dOffB + 16, as + 8);
            cp16(bBase[nb] + dOffB,      bs);
            cp16(bBase[nb] + dOffB + 16, bs + 8);
            asm volatile("cp.async.commit_group;");
            asm volatile("cp.async.wait_group 1;");
        } else {
            asm volatile("cp.async.wait_group 0;");
        }
        __syncthreads();

        const __half* a = As[buf];
        const __half* b = Bs[buf];
        #pragma unroll
        for (int ks = 0; ks < 2; ks++) {
            int kk = ks * 16;
            uint32_t af[4][4], bf[4][2];
            #pragma unroll
            for (int mf = 0; mf < 4; mf++) {
                int r = wm + mf * 16 + g;
                af[mf][0] = *(const uint32_t*)&a[ r      * SMS + kk + c2];
                af[mf][1] = *(const uint32_t*)&a[(r + 8) * SMS + kk + c2];
                af[mf][2] = *(const uint32_t*)&a[ r      * SMS + kk + c2 + 8];
                af[mf][3] = *(const uint32_t*)&a[(r + 8) * SMS + kk + c2 + 8];
            }
            #pragma unroll
            for (int nf = 0; nf < 4; nf++) {
                int n = wn + nf * 8 + g;
                bf[nf][0] = *(const uint32_t*)&b[n * SMS + kk + c2];
                bf[nf][1] = *(const uint32_t*)&b[n * SMS + kk + c2 + 8];
            }
            #pragma unroll
            for (int mf = 0; mf < 4; mf++)
                #pragma unroll
                for (int nf = 0; nf < 4; nf++)
                    mma_f16(acc[mf][nf], af[mf], bf[nf]);
        }
        __syncthreads();
    }

    // epilogue
    #pragma unroll
    for (int mf = 0; mf < 4; mf++) {
        int r = row0 + wm + mf * 16 + g;
        #pragma unroll
        for (int nf = 0; nf < 4; nf++) {
            int c = n0 + wn + nf * 8 + c2;
            float v0 = acc[mf][nf][0], v1 = acc[mf][nf][1];
            float v2 = acc[mf][nf][2], v3 = acc[mf][nf][3];
            if (RELU2) {
                v0 = fmaxf(v0, 0.f); v0 *= v0;
                v1 = fmaxf(v1, 0.f); v1 *= v1;
                v2 = fmaxf(v2, 0.f); v2 *= v2;
                v3 = fmaxf(v3, 0.f); v3 *= v3;
            }
            if (sizeof(CT) == 2) {
                __half2 lo = __floats2half2_rn(v0, v1);
                __half2 hi = __floats2half2_rn(v2, v3);
                *(uint32_t*)((__half*)C + (size_t) r      * Ntot + c) = *(uint32_t*)&lo;
                *(uint32_t*)((__half*)C + (size_t)(r + 8) * Ntot + c) = *(uint32_t*)&hi;
            } else {
                float2 lo; lo.x = v0; lo.y = v1;
                float2 hi; hi.x = v2; hi.y = v3;
                *(float2*)((float*)C + (size_t) r      * Ntot + c) = lo;
                *(float2*)((float*)C + (size_t)(r + 8) * Ntot + c) = hi;
            }
        }
    }
}

// ---------------- combine ----------------
__global__ void combine_kernel(float* __restrict__ out) {
    int t = blockIdx.x;
    int h = threadIdx.x * 4;
    float4 o = *(const float4*)&g_ys[(size_t)t * HDIM + h];
    #pragma unroll
    for (int j = 0; j < TOPK; j++) {
        int slot = g_slotmap[t*TOPK + j];
        float w = g_topw[t*TOPK + j];
        float4 v = *(const float4*)&g_y[(size_t)slot * HDIM + h];
        o.x += w * v.x; o.y += w * v.y; o.z += w * v.z; o.w += w * v.w;
    }
    *(float4*)&out[(size_t)t * HDIM + h] = o;
}

// ---------------- launch ----------------
extern "C" void kernel_launch(void* const* d_in, const int* in_sizes, int n_in,
                              void* d_out, int out_size) {
    const float *x = 0, *Wg = 0, *bias = 0, *W1 = 0, *W2 = 0, *Ws1 = 0, *Ws2 = 0;
    for (int i = 0; i < n_in; i++) {
        int sz = in_sizes[i];
        const float* p = (const float*)d_in[i];
        if      (sz == 2097152) { x = p; }
        else if (sz == 16384)   { Wg = p; }
        else if (sz == 16)      { bias = p; }
        else if (sz == 8388608) { if (!W1) W1 = p; else W2 = p; }
        else if (sz == 1048576) { if (!Ws1) Ws1 = p; else Ws2 = p; }
    }
    if (!x || !Wg || !bias || !W1 || !W2 || !Ws1 || !Ws2) {
        x = (const float*)d_in[0]; Wg = (const float*)d_in[1]; bias = (const float*)d_in[2];
        W1 = (const float*)d_in[3]; W2 = (const float*)d_in[4];
        Ws1 = (const float*)d_in[5]; Ws2 = (const float*)d_in[6];
    }
    float* out = (float*)d_out;

    __half *p_hx, *p_hW1, *p_hW2, *p_hWs1, *p_hWs2, *p_hid, *p_hs;
    float *p_y, *p_ys;
    cudaGetSymbolAddress((void**)&p_hx,   h_x);
    cudaGetSymbolAddress((void**)&p_hW1,  h_W1);
    cudaGetSymbolAddress((void**)&p_hW2,  h_W2);
    cudaGetSymbolAddress((void**)&p_hWs1, h_Ws1);
    cudaGetSymbolAddress((void**)&p_hWs2, h_Ws2);
    cudaGetSymbolAddress((void**)&p_hid,  g_hid);
    cudaGetSymbolAddress((void**)&p_hs,   g_hs);
    cudaGetSymbolAddress((void**)&p_y,    g_y);
    cudaGetSymbolAddress((void**)&p_ys,   g_ys);

    init_kernel<<<(MAXSLOTS + 255) / 256, 256>>>();
    router_kernel<<<T_TOK, 128>>>(x, Wg, bias);
    scan_kernel<<<1, 32>>>();
    fill_kernel<<<(T_TOK + 255) / 256, 256>>>();

    // fp32 -> fp16 conversions
    cvt_kernel<<<1024, 256>>>(x,   p_hx,   T_TOK*HDIM/4);
    cvt_kernel<<<2048, 256>>>(W1,  p_hW1,  NEXP*IDIM*HDIM/4);
    cvt_kernel<<<2048, 256>>>(W2,  p_hW2,  NEXP*HDIM*IDIM/4);
    cvt_kernel<<<512,  256>>>(Ws1, p_hWs1, ISDIM*HDIM/4);
    cvt_kernel<<<512,  256>>>(Ws2, p_hWs2, HDIM*ISDIM/4);

    // expert up: hid[slot] = relu2( x[g_list[slot]] @ W1[e]^T )  (fp16 out)
    gemm_h<true,  true,  true,  __half><<<dim3(MAXSLOTS/BM, IDIM/BN),  256>>>(p_hx,  p_hW1,  p_hid, HDIM,  IDIM,  (size_t)IDIM*HDIM);
    // expert down: y[slot] = hid[slot] @ W2[e]^T  (fp32 out)
    gemm_h<false, true,  false, float ><<<dim3(MAXSLOTS/BM, HDIM/BN),  256>>>(p_hid, p_hW2,  p_y,   IDIM,  HDIM,  (size_t)HDIM*IDIM);
    // shared up: hs[t] = relu2( x[t] @ Ws1^T )  (fp16 out)
    gemm_h<false, false, true,  __half><<<dim3(T_TOK/BM,   ISDIM/BN), 256>>>(p_hx,  p_hWs1, p_hs,  HDIM,  ISDIM, 0);
    // shared down: ys[t] = hs[t] @ Ws2^T  (fp32 out)
    gemm_h<false, false, false, float ><<<dim3(T_TOK/BM,   HDIM/BN),  256>>>(p_hs,  p_hWs2, p_ys,  ISDIM, HDIM,  0);

    combine_kernel<<<T_TOK, 256>>>(out);
}

// round 10
// speedup vs baseline: 10.1437x; 1.0259x over previous
#include <cuda_runtime.h>
#include <cuda_fp16.h>
#include <math.h>
#include <stdint.h>

// Problem constants
#define T_TOK   2048
#define HDIM    1024
#define NEXP    16
#define IDIM    512
#define ISDIM   1024
#define TOPK    4
#define NGRP    4
#define EPG     4
#define SCALE_F 2.5f

#define BM 128
#define BN 128
#define BK 32
#define MAXSLOTS (8192 + NEXP*BM)    // 10240
#define SMS 40                        // smem stride in halves (32 + 8 pad)
#define TILEH (128 * SMS)             // halves per stage per operand
#define STAGE_BYTES (TILEH * 2)
#define NSTAGE 3
#define SMEM_TOTAL (2 * NSTAGE * STAGE_BYTES)   // 61440 B

// ---------------- scratch ----------------
__device__ float  g_topw[T_TOK*TOPK];
__device__ int    g_tope[T_TOK*TOPK];
__device__ int    g_slotmap[T_TOK*TOPK];
__device__ int    g_list[MAXSLOTS];
__device__ int    g_cnt[NEXP];
__device__ int    g_cur[NEXP];
__device__ int    g_off[NEXP+1];

__device__ __half h_x  [(size_t)T_TOK * HDIM];
__device__ __half h_W1 [(size_t)NEXP * IDIM * HDIM];
__device__ __half h_W2 [(size_t)NEXP * HDIM * IDIM];
__device__ __half h_Ws1[(size_t)ISDIM * HDIM];
__device__ __half h_Ws2[(size_t)HDIM * ISDIM];

__device__ __half g_hid[(size_t)MAXSLOTS * IDIM];
__device__ float  g_y  [(size_t)MAXSLOTS * HDIM];
__device__ __half g_hs [(size_t)T_TOK * ISDIM];
__device__ float  g_ys [(size_t)T_TOK * HDIM];

// ---------------- helpers ----------------
__device__ __forceinline__ uint32_t smem_u32(const void* p) {
    uint32_t a;
    asm("{ .reg .u64 t; cvta.to.shared.u64 t, %1; cvt.u32.u64 %0, t; }" : "=r"(a) : "l"(p));
    return a;
}
__device__ __forceinline__ void cp16(uint32_t dst, const void* src) {
    asm volatile("cp.async.cg.shared.global [%0], [%1], 16;" :: "r"(dst), "l"(src));
}
__device__ __forceinline__ void ldsm_x4(uint32_t* r, uint32_t addr) {
    asm volatile("ldmatrix.sync.aligned.m8n8.x4.shared.b16 {%0,%1,%2,%3}, [%4];"
                 : "=r"(r[0]), "=r"(r[1]), "=r"(r[2]), "=r"(r[3]) : "r"(addr));
}
__device__ __forceinline__ void mma_f16(float* c, const uint32_t* a, const uint32_t* b) {
    asm volatile(
        "mma.sync.aligned.m16n8k16.row.col.f32.f16.f16.f32 "
        "{%0,%1,%2,%3}, {%4,%5,%6,%7}, {%8,%9}, {%0,%1,%2,%3};"
        : "+f"(c[0]), "+f"(c[1]), "+f"(c[2]), "+f"(c[3])
        : "r"(a[0]), "r"(a[1]), "r"(a[2]), "r"(a[3]), "r"(b[0]), "r"(b[1]));
}

// ---------------- fp32 -> fp16 ----------------
__global__ void cvt_kernel(const float* __restrict__ src, __half* __restrict__ dst, int n4) {
    int i = blockIdx.x * 256 + threadIdx.x;
    int stride = gridDim.x * 256;
    for (; i < n4; i += stride) {
        float4 v = *(const float4*)(src + (size_t)i * 4);
        __half2 lo = __floats2half2_rn(v.x, v.y);
        __half2 hi = __floats2half2_rn(v.z, v.w);
        uint2 u;
        u.x = *(uint32_t*)&lo;
        u.y = *(uint32_t*)&hi;
        *(uint2*)(dst + (size_t)i * 4) = u;
    }
}

// ---------------- init ----------------
__global__ void init_kernel() {
    int i = blockIdx.x * 256 + threadIdx.x;
    if (i < NEXP) { g_cnt[i] = 0; g_cur[i] = 0; }
    if (i < MAXSLOTS) g_list[i] = -1;
}

// ---------------- router ----------------
__global__ void router_kernel(const float* __restrict__ x,
                              const float* __restrict__ Wg,
                              const float* __restrict__ bias) {
    int t = blockIdx.x;
    __shared__ float sx[HDIM];
    __shared__ float slog[NEXP];
    const float* xr = x + (size_t)t * HDIM;
    for (int i = threadIdx.x; i < HDIM; i += 128) sx[i] = xr[i];
    __syncthreads();
    int warp = threadIdx.x >> 5, lane = threadIdx.x & 31;
    for (int eo = 0; eo < 4; eo++) {
        int e = warp * 4 + eo;
        const float* w = Wg + (size_t)e * HDIM;
        float p = 0.f;
        for (int i = lane; i < HDIM; i += 32) p += sx[i] * w[i];
        #pragma unroll
        for (int o = 16; o; o >>= 1) p += __shfl_xor_sync(0xffffffffu, p, o);
        if (lane == 0) slog[e] = p;
    }
    __syncthreads();
    if (threadIdx.x == 0) {
        float sc[NEXP], ch[NEXP];
        #pragma unroll
        for (int e = 0; e < NEXP; e++) {
            sc[e] = 1.f / (1.f + expf(-slog[e]));
            ch[e] = sc[e] + bias[e];
        }
        float gs[NGRP];
        #pragma unroll
        for (int g = 0; g < NGRP; g++) {
            float m1 = -1e30f, m2 = -1e30f;
            #pragma unroll
            for (int k = 0; k < EPG; k++) {
                float v = ch[g*EPG + k];
                if (v > m1) { m2 = m1; m1 = v; } else if (v > m2) { m2 = v; }
            }
            gs[g] = m1 + m2;
        }
        int g1 = 0;
        for (int g = 1; g < NGRP; g++) if (gs[g] > gs[g1]) g1 = g;
        int g2 = -1;
        for (int g = 0; g < NGRP; g++) { if (g == g1) continue; if (g2 < 0 || gs[g] > gs[g2]) g2 = g; }
        float masked[NEXP];
        #pragma unroll
        for (int e = 0; e < NEXP; e++) {
            int g = e >> 2;
            masked[e] = (g == g1 || g == g2) ? ch[e] : 0.f;
        }
        int idx[TOPK]; float tw[TOPK]; float wsum = 0.f;
        #pragma unroll
        for (int j = 0; j < TOPK; j++) {
            int b = 0;
            for (int e = 1; e < NEXP; e++) if (masked[e] > masked[b]) b = e;
            idx[j] = b; tw[j] = sc[b]; wsum += sc[b];
            masked[b] = -1e30f;
        }
        float inv = SCALE_F / (wsum + 1e-20f);
        #pragma unroll
        for (int j = 0; j < TOPK; j++) {
            g_topw[t*TOPK + j] = tw[j] * inv;
            g_tope[t*TOPK + j] = idx[j];
            atomicAdd(&g_cnt[idx[j]], 1);
        }
    }
}

__global__ void scan_kernel() {
    if (threadIdx.x == 0) {
        int o = 0;
        for (int e = 0; e < NEXP; e++) {
            g_off[e] = o;
            o += ((g_cnt[e] + BM - 1) / BM) * BM;
        }
        g_off[NEXP] = o;
    }
}

__global__ void fill_kernel() {
    int t = blockIdx.x * 256 + threadIdx.x;
    if (t >= T_TOK) return;
    for (int j = 0; j < TOPK; j++) {
        int e = g_tope[t*TOPK + j];
        int pos = atomicAdd(&g_cur[e], 1);
        int slot = g_off[e] + pos;
        g_list[slot] = t;
        g_slotmap[t*TOPK + j] = slot;
    }
}

// ---------------- fp16 tensor-core GEMM (ldmatrix + 3-stage cp.async) ----------------
// C[row][n] = act( A_row . W[n] ); A [.,K] fp16 row-major, W [N,K] fp16 row-major.
// BM=BN=128, BK=32, 256 threads = 8 warps (2m x 4n), warp tile 64x32.
template<bool GATHER, bool EXPERT, bool RELU2, typename CT>
__global__ void __launch_bounds__(256)
gemm_h(const __half* __restrict__ A, const __half* __restrict__ W,
       CT* __restrict__ C, int K, int Ntot, size_t wstride) {
    extern __shared__ __align__(16) __half dsm[];
    int row0 = blockIdx.x * BM;
    int e = 0;
    if (EXPERT) {
        int tot = g_off[NEXP];
        if (row0 >= tot) return;
        while (row0 >= g_off[e+1]) e++;
    }
    const __half* Wb = EXPERT ? (W + (size_t)e * wstride) : W;
    int n0 = blockIdx.y * BN;

    int tid  = threadIdx.x;
    int lane = tid & 31;
    int warp = tid >> 5;
    int wm = (warp & 1) * 64;
    int wn = (warp >> 1) * 32;

    // stage bases
    uint32_t s0 = smem_u32(dsm);
    uint32_t aB[NSTAGE], bB[NSTAGE];
    #pragma unroll
    for (int s = 0; s < NSTAGE; s++) {
        aB[s] = s0 + s * STAGE_BYTES;
        bB[s] = s0 + (NSTAGE + s) * STAGE_BYTES;
    }

    // loader mapping: thread owns one row, 32B (two cp16)
    int lrow = tid >> 1;
    int lcol = (tid & 1) * 16;                       // half offset 0/16
    uint32_t dOff = (uint32_t)(lrow * SMS + lcol) * 2;

    const __half* arow;
    if (GATHER) {
        int tok = g_list[row0 + lrow];
        arow = A + (size_t)(tok >= 0 ? tok : 0) * K;
    } else {
        arow = A + (size_t)(row0 + lrow) * K;
    }
    const __half* brow = Wb + (size_t)(n0 + lrow) * K;

    // ldmatrix lane address components (byte offsets within a stage)
    // A tile mf: row = wm + mf*16 + (lane&15), colhalf (lane>>4)*8
    uint32_t aOff = (uint32_t)((wm + (lane & 15)) * SMS + (lane >> 4) * 8) * 2;
    // B pair nfp: n = wn + nfp*16 + (lane>>4)*8 + (lane&7), khalf ((lane>>3)&1)*8
    uint32_t bOff = (uint32_t)((wn + ((lane >> 4) * 8) + (lane & 7)) * SMS + ((lane >> 3) & 1) * 8) * 2;

    float acc[4][4][4];
    #pragma unroll
    for (int i = 0; i < 4; i++)
        #pragma unroll
        for (int j = 0; j < 4; j++)
            #pragma unroll
            for (int q = 0; q < 4; q++) acc[i][j][q] = 0.f;

    int nt = K / BK;

    // prologue: issue tiles 0,1
    #pragma unroll
    for (int p = 0; p < 2; p++) {
        const __half* as = arow + p * BK + lcol;
        const __half* bs = brow + p * BK + lcol;
        cp16(aB[p] + dOff,      as);
        cp16(aB[p] + dOff + 16, as + 8);
        cp16(bB[p] + dOff,      bs);
        cp16(bB[p] + dOff + 16, bs + 8);
        asm volatile("cp.async.commit_group;");
    }

    for (int kt = 0; kt < nt; kt++) {
        if (kt + 1 < nt) asm volatile("cp.async.wait_group 1;");
        else             asm volatile("cp.async.wait_group 0;");
        __syncthreads();

        // issue tile kt+2 into stage (kt+2)%3 (its previous readers finished pre-sync)
        if (kt + 2 < nt) {
            int s = (kt + 2) % NSTAGE;
            const __half* as = arow + (kt + 2) * BK + lcol;
            const __half* bs = brow + (kt + 2) * BK + lcol;
            cp16(aB[s] + dOff,      as);
            cp16(aB[s] + dOff + 16, as + 8);
            cp16(bB[s] + dOff,      bs);
            cp16(bB[s] + dOff + 16, bs + 8);
            asm volatile("cp.async.commit_group;");
        }

        int buf = kt % NSTAGE;
        uint32_t aT = aB[buf], bT = bB[buf];
        #pragma unroll
        for (int ks = 0; ks < 2; ks++) {
            uint32_t kkB = (uint32_t)(ks * 16) * 2;
            uint32_t af[4][4], bf[4][2];
            #pragma unroll
            for (int mf = 0; mf < 4; mf++)
                ldsm_x4(af[mf], aT + aOff + (uint32_t)(mf * 16 * SMS) * 2 + kkB);
            #pragma unroll
            for (int nfp = 0; nfp < 2; nfp++) {
                uint32_t r[4];
                ldsm_x4(r, bT + bOff + (uint32_t)(nfp * 16 * SMS) * 2 + kkB);
                bf[nfp*2+0][0] = r[0]; bf[nfp*2+0][1] = r[1];
                bf[nfp*2+1][0] = r[2]; bf[nfp*2+1][1] = r[3];
            }
            #pragma unroll
            for (int mf = 0; mf < 4; mf++)
                #pragma unroll
                for (int nf = 0; nf < 4; nf++)
                    mma_f16(acc[mf][nf], af[mf], bf[nf]);
        }
        __syncthreads();
    }

    // epilogue
    int g  = lane >> 2;
    int c2 = (lane & 3) * 2;
    #pragma unroll
    for (int mf = 0; mf < 4; mf++) {
        int r = row0 + wm + mf * 16 + g;
        #pragma unroll
        for (int nf = 0; nf < 4; nf++) {
            int c = n0 + wn + nf * 8 + c2;
            float v0 = acc[mf][nf][0], v1 = acc[mf][nf][1];
            float v2 = acc[mf][nf][2], v3 = acc[mf][nf][3];
            if (RELU2) {
                v0 = fmaxf(v0, 0.f); v0 *= v0;
                v1 = fmaxf(v1, 0.f); v1 *= v1;
                v2 = fmaxf(v2, 0.f); v2 *= v2;
                v3 = fmaxf(v3, 0.f); v3 *= v3;
            }
            if (sizeof(CT) == 2) {
                __half2 lo = __floats2half2_rn(v0, v1);
                __half2 hi = __floats2half2_rn(v2, v3);
                *(uint32_t*)((__half*)C + (size_t) r      * Ntot + c) = *(uint32_t*)&lo;
                *(uint32_t*)((__half*)C + (size_t)(r + 8) * Ntot + c) = *(uint32_t*)&hi;
            } else {
                float2 lo; lo.x = v0; lo.y = v1;
                float2 hi; hi.x = v2; hi.y = v3;
                *(float2*)((float*)C + (size_t) r      * Ntot + c) = lo;
                *(float2*)((float*)C + (size_t)(r + 8) * Ntot + c) = hi;
            }
        }
    }
}

// ---------------- combine ----------------
__global__ void combine_kernel(float* __restrict__ out) {
    int t = blockIdx.x;
    int h = threadIdx.x * 4;
    float4 o = *(const float4*)&g_ys[(size_t)t * HDIM + h];
    #pragma unroll
    for (int j = 0; j < TOPK; j++) {
        int slot = g_slotmap[t*TOPK + j];
        float w = g_topw[t*TOPK + j];
        float4 v = *(const float4*)&g_y[(size_t)slot * HDIM + h];
        o.x += w * v.x; o.y += w * v.y; o.z += w * v.z; o.w += w * v.w;
    }
    *(float4*)&out[(size_t)t * HDIM + h] = o;
}

// ---------------- launch ----------------
extern "C" void kernel_launch(void* const* d_in, const int* in_sizes, int n_in,
                              void* d_out, int out_size) {
    const float *x = 0, *Wg = 0, *bias = 0, *W1 = 0, *W2 = 0, *Ws1 = 0, *Ws2 = 0;
    for (int i = 0; i < n_in; i++) {
        int sz = in_sizes[i];
        const float* p = (const float*)d_in[i];
        if      (sz == 2097152) { x = p; }
        else if (sz == 16384)   { Wg = p; }
        else if (sz == 16)      { bias = p; }
        else if (sz == 8388608) { if (!W1) W1 = p; else W2 = p; }
        else if (sz == 1048576) { if (!Ws1) Ws1 = p; else Ws2 = p; }
    }
    if (!x || !Wg || !bias || !W1 || !W2 || !Ws1 || !Ws2) {
        x = (const float*)d_in[0]; Wg = (const float*)d_in[1]; bias = (const float*)d_in[2];
        W1 = (const float*)d_in[3]; W2 = (const float*)d_in[4];
        Ws1 = (const float*)d_in[5]; Ws2 = (const float*)d_in[6];
    }
    float* out = (float*)d_out;

    __half *p_hx, *p_hW1, *p_hW2, *p_hWs1, *p_hWs2, *p_hid, *p_hs;
    float *p_y, *p_ys;
    cudaGetSymbolAddress((void**)&p_hx,   h_x);
    cudaGetSymbolAddress((void**)&p_hW1,  h_W1);
    cudaGetSymbolAddress((void**)&p_hW2,  h_W2);
    cudaGetSymbolAddress((void**)&p_hWs1, h_Ws1);
    cudaGetSymbolAddress((void**)&p_hWs2, h_Ws2);
    cudaGetSymbolAddress((void**)&p_hid,  g_hid);
    cudaGetSymbolAddress((void**)&p_hs,   g_hs);
    cudaGetSymbolAddress((void**)&p_y,    g_y);
    cudaGetSymbolAddress((void**)&p_ys,   g_ys);

    cudaFuncSetAttribute(gemm_h<true,  true,  true,  __half>, cudaFuncAttributeMaxDynamicSharedMemorySize, SMEM_TOTAL);
    cudaFuncSetAttribute(gemm_h<false, true,  false, float >, cudaFuncAttributeMaxDynamicSharedMemorySize, SMEM_TOTAL);
    cudaFuncSetAttribute(gemm_h<false, false, true,  __half>, cudaFuncAttributeMaxDynamicSharedMemorySize, SMEM_TOTAL);
    cudaFuncSetAttribute(gemm_h<false, false, false, float >, cudaFuncAttributeMaxDynamicSharedMemorySize, SMEM_TOTAL);

    init_kernel<<<(MAXSLOTS + 255) / 256, 256>>>();
    router_kernel<<<T_TOK, 128>>>(x, Wg, bias);
    scan_kernel<<<1, 32>>>();
    fill_kernel<<<(T_TOK + 255) / 256, 256>>>();

    cvt_kernel<<<1024, 256>>>(x,   p_hx,   T_TOK*HDIM/4);
    cvt_kernel<<<2048, 256>>>(W1,  p_hW1,  NEXP*IDIM*HDIM/4);
    cvt_kernel<<<2048, 256>>>(W2,  p_hW2,  NEXP*HDIM*IDIM/4);
    cvt_kernel<<<512,  256>>>(Ws1, p_hWs1, ISDIM*HDIM/4);
    cvt_kernel<<<512,  256>>>(Ws2, p_hWs2, HDIM*ISDIM/4);

    // expert up: hid[slot] = relu2( x[g_list[slot]] @ W1[e]^T )  (fp16 out)
    gemm_h<true,  true,  true,  __half><<<dim3(MAXSLOTS/BM, IDIM/BN),  256, SMEM_TOTAL>>>(p_hx,  p_hW1,  p_hid, HDIM,  IDIM,  (size_t)IDIM*HDIM);
    // expert down: y[slot] = hid[slot] @ W2[e]^T  (fp32 out)
    gemm_h<false, true,  false, float ><<<dim3(MAXSLOTS/BM, HDIM/BN),  256, SMEM_TOTAL>>>(p_hid, p_hW2,  p_y,   IDIM,  HDIM,  (size_t)HDIM*IDIM);
    // shared up: hs[t] = relu2( x[t] @ Ws1^T )  (fp16 out)
    gemm_h<false, false, true,  __half><<<dim3(T_TOK/BM,   ISDIM/BN), 256, SMEM_TOTAL>>>(p_hx,  p_hWs1, p_hs,  HDIM,  ISDIM, 0);
    // shared down: ys[t] = hs[t] @ Ws2^T  (fp32 out)
    gemm_h<false, false, false, float ><<<dim3(T_TOK/BM,   HDIM/BN),  256, SMEM_TOTAL>>>(p_hs,  p_hWs2, p_ys,  ISDIM, HDIM,  0);

    combine_kernel<<<T_TOK, 256>>>(out);
}